// round 2
// baseline (speedup 1.0000x reference)
#include <cuda_runtime.h>
#include <math.h>

// ---------------- device scratch (static: allocations are forbidden) -------
__device__ float g_Keff[24 * 16384];   // [par(8)][br(3)][c(64)][tap(8)][co(32)]
__device__ float g_wc2T[3072];         // [c'(96)][o(32)]  (w_comb * s2, transposed)
__device__ float g_bias1[32];
__device__ float g_bias2[32];

// ---------------- f32x2 helpers --------------------------------------------
__device__ __forceinline__ void fma2(unsigned long long& d, unsigned long long a,
                                     unsigned long long b) {
    asm("fma.rn.f32x2 %0, %1, %2, %0;" : "+l"(d) : "l"(a), "l"(b));
}
__device__ __forceinline__ unsigned long long pack2(float v) {
    unsigned long long r;
    asm("mov.b64 %0, {%1, %1};" : "=l"(r) : "f"(v));
    return r;
}
__device__ __forceinline__ float2 unpack2(unsigned long long v) {
    float2 r;
    asm("mov.b64 {%0, %1}, %2;" : "=f"(r.x), "=f"(r.y) : "l"(v));
    return r;
}

// ---------------- setup: fold BN2 into combine weights / biases ------------
__global__ void fold_params(const float* __restrict__ b_def,
                            const float* __restrict__ g1, const float* __restrict__ b1,
                            const float* __restrict__ m1, const float* __restrict__ v1,
                            const float* __restrict__ wcm, const float* __restrict__ bcm,
                            const float* __restrict__ g2, const float* __restrict__ b2,
                            const float* __restrict__ m2, const float* __restrict__ v2) {
    int tid = threadIdx.x;
    if (tid < 32) {
        float s1 = g1[tid] * rsqrtf(v1[tid] + 1e-5f);
        g_bias1[tid] = b_def[tid] * s1 + b1[tid] - m1[tid] * s1;
        float s2 = g2[tid] * rsqrtf(v2[tid] + 1e-5f);
        g_bias2[tid] = bcm[tid] * s2 + b2[tid] - m2[tid] * s2;
    }
    for (int idx = tid; idx < 3072; idx += blockDim.x) {
        int o = idx & 31, cp = idx >> 5;
        float s2 = g2[o] * rsqrtf(v2[o] + 1e-5f);
        g_wc2T[idx] = wcm[o * 96 + cp] * s2;
    }
}

// per-axis trilinear->original-grid collapse weights
__device__ __forceinline__ double hval(int q, int k, int e, double a) {
    if (q == 0) {
        if (k == 0) return e ? a : (1.0 - a);
        return e ? 1.0 : 0.0;          // k=1,2 -> x[P]
    } else {
        if (k == 2) return e ? (1.0 - a) : a;
        return e ? 0.0 : 1.0;          // k=0,1 -> x[P]
    }
}

// ---------------- setup: effective 2x2x2 kernels (BN1 scale folded) --------
__global__ void make_keff(const float* __restrict__ W,
                          const float* __restrict__ g1, const float* __restrict__ v1) {
    __shared__ float ws[32 * 27];
    int c = blockIdx.x;
    int par = blockIdx.y / 3, br = blockIdx.y % 3;
    int tap = threadIdx.x >> 5, co = threadIdx.x & 31;

    for (int idx = threadIdx.x; idx < 32 * 27; idx += 256) {
        int cco = idx / 27, kk = idx - cco * 27;
        ws[idx] = W[(cco * 64 + c) * 27 + kk];
    }
    __syncthreads();

    double a = (br == 0) ? 0.0 : (br == 1 ? 0.4 : 0.7);
    int ez = (tap >> 2) & 1, ey = (tap >> 1) & 1, ex = tap & 1;
    int qz = (par >> 2) & 1, qy = (par >> 1) & 1, qx = par & 1;

    double hz[3], hy[3], hx[3];
#pragma unroll
    for (int k = 0; k < 3; k++) {
        hz[k] = hval(qz, k, ez, a);
        hy[k] = hval(qy, k, ey, a);
        hx[k] = hval(qx, k, ex, a);
    }
    float sum = 0.f;
#pragma unroll
    for (int kz = 0; kz < 3; kz++)
#pragma unroll
        for (int ky = 0; ky < 3; ky++)
#pragma unroll
            for (int kx = 0; kx < 3; kx++) {
                float wt = (float)(hz[kz] * hy[ky] * hx[kx]);
                sum += ws[co * 27 + kz * 9 + ky * 3 + kx] * wt;
            }
    float s1 = g1[co] * rsqrtf(v1[co] + 1e-5f);
    g_Keff[(((par * 3 + br) * 64 + c) * 8 + tap) * 32 + co] = sum * s1;
}

// ---------------- main fused kernel -----------------------------------------
// block: 256 threads = 8(x) x 8(y) x 4(z) original-coord tile, ONE parity class
// smem: x tile [64c][5z][9y][9x] + Keff slice [64c][8tap][32co] + wc2T + biases
#define XS_FLOATS 25920   // 64*405
#define KF_FLOATS 16384
#define WC_FLOATS 3072
#define SMEM_BYTES ((XS_FLOATS + KF_FLOATS + WC_FLOATS + 64) * 4)

__global__ void __launch_bounds__(256)
conv_main(const float* __restrict__ x, float* __restrict__ out) {
    extern __shared__ float sm[];
    float* xs = sm;                         // 25920
    float* kf = sm + XS_FLOATS;             // 16384
    float* wc = sm + XS_FLOATS + KF_FLOATS; // 3072
    float* b1 = wc + WC_FLOATS;             // 32
    float* b2 = b1 + 32;                    // 32

    const int tid = threadIdx.x;
    const int lx = tid & 7, ly = (tid >> 3) & 7, lz = tid >> 6;

    const int par = blockIdx.z >> 3;
    const int pzt = blockIdx.z & 7;
    const int qz = (par >> 2) & 1, qy = (par >> 1) & 1, qx = par & 1;

    const int Px0 = blockIdx.x * 8, Py0 = blockIdx.y * 8, Pz0 = pzt * 4;
    const int ox = Px0 - 1 + qx, oy = Py0 - 1 + qy, oz = Pz0 - 1 + qz;

    // ---- load x tile (zero-filled at borders) ----
    for (int idx = tid; idx < XS_FLOATS; idx += 256) {
        int c = idx / 405;
        int r = idx - c * 405;
        int z = r / 81; r -= z * 81;
        int y = r / 9;  int xx = r - y * 9;
        int gz = oz + z, gy = oy + y, gx = ox + xx;
        float v = 0.f;
        if ((unsigned)gz < 32u && (unsigned)gy < 32u && (unsigned)gx < 32u)
            v = x[((c * 32 + gz) * 32 + gy) * 32 + gx];
        xs[idx] = v;
    }
    for (int idx = tid; idx < WC_FLOATS; idx += 256) wc[idx] = g_wc2T[idx];
    if (tid < 32) { b1[tid] = g_bias1[tid]; b2[tid] = g_bias2[tid]; }

    unsigned long long outacc[16];
#pragma unroll
    for (int i = 0; i < 16; i++) outacc[i] = 0ull;

    const int xbase = lz * 81 + ly * 9 + lx;

    for (int br = 0; br < 3; br++) {
        __syncthreads();
        const float* src = g_Keff + (par * 3 + br) * KF_FLOATS;
        for (int idx = tid; idx < KF_FLOATS; idx += 256) kf[idx] = src[idx];
        __syncthreads();

        unsigned long long acc[16];
#pragma unroll
        for (int i = 0; i < 16; i++) acc[i] = 0ull;

#pragma unroll 1
        for (int c = 0; c < 64; c++) {
            const float* xp = xs + c * 405 + xbase;
            unsigned long long xb[8];
            xb[0] = pack2(xp[0]);  xb[1] = pack2(xp[1]);
            xb[2] = pack2(xp[9]);  xb[3] = pack2(xp[10]);
            xb[4] = pack2(xp[81]); xb[5] = pack2(xp[82]);
            xb[6] = pack2(xp[90]); xb[7] = pack2(xp[91]);
            const ulonglong2* kq = (const ulonglong2*)(kf + c * 256);
#pragma unroll
            for (int t = 0; t < 8; t++) {
#pragma unroll
                for (int j = 0; j < 8; j++) {
                    ulonglong2 k2 = kq[t * 8 + j];
                    fma2(acc[2 * j],     k2.x, xb[t]);
                    fma2(acc[2 * j + 1], k2.y, xb[t]);
                }
            }
        }

        // ---- ReLU + fold this branch into the combine accumulators ----
#pragma unroll
        for (int i = 0; i < 16; i++) {
            float2 a2 = unpack2(acc[i]);
            float rv0 = fmaxf(a2.x + b1[2 * i], 0.f);
            float rv1 = fmaxf(a2.y + b1[2 * i + 1], 0.f);
            {
                unsigned long long rp = pack2(rv0);
                const ulonglong2* w2 = (const ulonglong2*)(wc + (br * 32 + 2 * i) * 32);
#pragma unroll
                for (int j = 0; j < 8; j++) {
                    ulonglong2 ww = w2[j];
                    fma2(outacc[2 * j],     ww.x, rp);
                    fma2(outacc[2 * j + 1], ww.y, rp);
                }
            }
            {
                unsigned long long rp = pack2(rv1);
                const ulonglong2* w2 = (const ulonglong2*)(wc + (br * 32 + 2 * i + 1) * 32);
#pragma unroll
                for (int j = 0; j < 8; j++) {
                    ulonglong2 ww = w2[j];
                    fma2(outacc[2 * j],     ww.x, rp);
                    fma2(outacc[2 * j + 1], ww.y, rp);
                }
            }
        }
    }

    // ---- bias2 + ReLU + store (upsampled coords) ----
    const int gx = 2 * (Px0 + lx) + qx;
    const int gy = 2 * (Py0 + ly) + qy;
    const int gz = 2 * (Pz0 + lz) + qz;
    float* op = out + (gz * 64 + gy) * 64 + gx;
#pragma unroll
    for (int m = 0; m < 16; m++) {
        float2 f = unpack2(outacc[m]);
        op[(2 * m) * 262144]     = fmaxf(f.x + b2[2 * m], 0.f);
        op[(2 * m + 1) * 262144] = fmaxf(f.y + b2[2 * m + 1], 0.f);
    }
}

// ---------------- launch -----------------------------------------------------
extern "C" void kernel_launch(void* const* d_in, const int* in_sizes, int n_in,
                              void* d_out, int out_size) {
    const float* x      = (const float*)d_in[0];
    const float* w_def  = (const float*)d_in[1];
    const float* b_def  = (const float*)d_in[2];
    const float* bn1_g  = (const float*)d_in[3];
    const float* bn1_b  = (const float*)d_in[4];
    const float* bn1_m  = (const float*)d_in[5];
    const float* bn1_v  = (const float*)d_in[6];
    const float* w_comb = (const float*)d_in[7];
    const float* b_comb = (const float*)d_in[8];
    const float* bn2_g  = (const float*)d_in[9];
    const float* bn2_b  = (const float*)d_in[10];
    const float* bn2_m  = (const float*)d_in[11];
    const float* bn2_v  = (const float*)d_in[12];

    fold_params<<<1, 256>>>(b_def, bn1_g, bn1_b, bn1_m, bn1_v,
                            w_comb, b_comb, bn2_g, bn2_b, bn2_m, bn2_v);
    make_keff<<<dim3(64, 24), 256>>>(w_def, bn1_g, bn1_v);

    cudaFuncSetAttribute(conv_main, cudaFuncAttributeMaxDynamicSharedMemorySize,
                         SMEM_BYTES);
    conv_main<<<dim3(4, 4, 64), 256, SMEM_BYTES>>>(x, (float*)d_out);
}

// round 3
// speedup vs baseline: 3.5210x; 3.5210x over previous
#include <cuda_runtime.h>
#include <math.h>

// ---------------- device scratch (static: allocations are forbidden) -------
// Conv A operand, fragment-major for mma.m16n8k8 tf32:
// [par(8)][c(64)][mt(6)][lane(32)][reg(4)]  (tf32 bit patterns)
__device__ unsigned g_Afrag[8 * 64 * 6 * 32 * 4];
// Combine A operand, fragment-major: [k2(12)][mt(2)][lane(32)][reg(4)]
__device__ unsigned g_A2frag[12 * 2 * 32 * 4];
__device__ float g_bias1[32];
__device__ float g_bias2[32];

// ---------------- helpers ----------------------------------------------------
__device__ __forceinline__ unsigned f2tf(float f) {
    unsigned r;
    asm("cvt.rna.tf32.f32 %0, %1;" : "=r"(r) : "f"(f));
    return r;
}

__device__ __forceinline__ void mma_tf32(float* d, const unsigned* a,
                                         unsigned b0, unsigned b1) {
    asm volatile(
        "mma.sync.aligned.m16n8k8.row.col.f32.tf32.tf32.f32 "
        "{%0,%1,%2,%3}, {%4,%5,%6,%7}, {%8,%9}, {%0,%1,%2,%3};"
        : "+f"(d[0]), "+f"(d[1]), "+f"(d[2]), "+f"(d[3])
        : "r"(a[0]), "r"(a[1]), "r"(a[2]), "r"(a[3]), "r"(b0), "r"(b1));
}

__device__ __forceinline__ void cp_async16(unsigned dstS, const void* src) {
    asm volatile("cp.async.cg.shared.global [%0], [%1], 16;" :: "r"(dstS), "l"(src));
}

// ---------------- setup: biases + combine fragments -------------------------
__global__ void fold_params(const float* __restrict__ b_def,
                            const float* __restrict__ g1, const float* __restrict__ b1,
                            const float* __restrict__ m1, const float* __restrict__ v1,
                            const float* __restrict__ wcm, const float* __restrict__ bcm,
                            const float* __restrict__ g2, const float* __restrict__ b2,
                            const float* __restrict__ m2, const float* __restrict__ v2) {
    int tid = threadIdx.x;
    if (tid < 32) {
        float s1 = g1[tid] * rsqrtf(v1[tid] + 1e-5f);
        g_bias1[tid] = b_def[tid] * s1 + b1[tid] - m1[tid] * s1;
        float s2 = g2[tid] * rsqrtf(v2[tid] + 1e-5f);
        g_bias2[tid] = bcm[tid] * s2 + b2[tid] - m2[tid] * s2;
    }
    // A2 fragments: D2[32 o][96 cp], A row-major m16n8k8 fragment layout
    for (int idx = tid; idx < 12 * 2 * 32 * 4; idx += blockDim.x) {
        int r = idx & 3, lane = (idx >> 2) & 31, mt = (idx >> 7) & 1, k2 = idx >> 8;
        int g = lane >> 2, t = lane & 3;
        int m = mt * 16 + g + 8 * (r & 1);
        int cp = k2 * 8 + t + 4 * (r >> 1);
        float s2 = g2[m] * rsqrtf(v2[m] + 1e-5f);
        g_A2frag[idx] = f2tf(wcm[m * 96 + cp] * s2);
    }
}

// per-axis trilinear->original-grid collapse weights
__device__ __forceinline__ double hval(int q, int k, int e, double a) {
    if (q == 0) {
        if (k == 0) return e ? a : (1.0 - a);
        return e ? 1.0 : 0.0;
    } else {
        if (k == 2) return e ? (1.0 - a) : a;
        return e ? 0.0 : 1.0;
    }
}

// ---------------- setup: conv A fragments (BN1 scale folded) ----------------
// grid (64 c, 8 par), block 192 = 6 mt x 32 lanes
__global__ void make_keff(const float* __restrict__ W,
                          const float* __restrict__ g1, const float* __restrict__ v1) {
    __shared__ float ws[32 * 27];
    int c = blockIdx.x, par = blockIdx.y;
    int tid = threadIdx.x;
    for (int idx = tid; idx < 32 * 27; idx += 192) {
        int co = idx / 27, kk = idx - co * 27;
        ws[idx] = W[co * 1728 + c * 27 + kk];
    }
    __syncthreads();

    int mt = tid >> 5, lane = tid & 31;
    int g = lane >> 2, t = lane & 3;
    int qz = (par >> 2) & 1, qy = (par >> 1) & 1, qx = par & 1;

#pragma unroll
    for (int r = 0; r < 4; r++) {
        int m = mt * 16 + g + 8 * (r & 1);
        int tap = t + 4 * (r >> 1);
        int br = m >> 5, co = m & 31;
        double a = (br == 0) ? 0.0 : (br == 1 ? 0.4 : 0.7);
        int ez = (tap >> 2) & 1, ey = (tap >> 1) & 1, ex = tap & 1;

        double hz[3], hy[3], hx[3];
#pragma unroll
        for (int k = 0; k < 3; k++) {
            hz[k] = hval(qz, k, ez, a);
            hy[k] = hval(qy, k, ey, a);
            hx[k] = hval(qx, k, ex, a);
        }
        float sum = 0.f;
#pragma unroll
        for (int kz = 0; kz < 3; kz++)
#pragma unroll
            for (int ky = 0; ky < 3; ky++)
#pragma unroll
                for (int kx = 0; kx < 3; kx++)
                    sum += ws[co * 27 + kz * 9 + ky * 3 + kx] *
                           (float)(hz[kz] * hy[ky] * hx[kx]);
        float s1 = g1[co] * rsqrtf(v1[co] + 1e-5f);
        g_Afrag[(((par * 64 + c) * 6 + mt) * 32 + lane) * 4 + r] = f2tf(sum * s1);
    }
}

// ---------------- main fused kernel ------------------------------------------
// block 256 thr = 8 warps; tile = 8(x) x 8(y) x 4(z) orig coords = 256 voxels,
// one parity class. Conv GEMM D[96][256] then combine GEMM D2[32][256].
#define XT_FLOATS 25920          // x tile [64c][5z][9y][9x]; reused as R[96][264]
#define SA_FLOATS 12288          // 2 x (8c * 6mt * 32 * 4) double-buffered A
#define SA2_FLOATS 3072
#define SMEM_BYTES ((XT_FLOATS + SA_FLOATS + SA2_FLOATS + 64) * 4)
#define RSTRIDE 264

__global__ void __launch_bounds__(256)
conv_main(const float* __restrict__ x, float* __restrict__ out) {
    extern __shared__ float sm[];
    float* xt = sm;                                // also R after conv
    float* sA = sm + XT_FLOATS;
    float* sA2 = sm + XT_FLOATS + SA_FLOATS;
    float* b1s = sA2 + SA2_FLOATS;
    float* b2s = b1s + 32;

    const int tid = threadIdx.x;
    const int w = tid >> 5, lane = tid & 31;
    const int g = lane >> 2, t = lane & 3;

    const int par = blockIdx.z >> 3;
    const int pzt = blockIdx.z & 7;
    const int qz = (par >> 2) & 1, qy = (par >> 1) & 1, qx = par & 1;
    const int Px0 = blockIdx.x * 8, Py0 = blockIdx.y * 8, Pz0 = pzt * 4;
    const int ox = Px0 - 1 + qx, oy = Py0 - 1 + qy, oz = Pz0 - 1 + qz;

    // ---- load x tile (tf32-rounded, zero at borders) ----
    for (int idx = tid; idx < XT_FLOATS; idx += 256) {
        int c = idx / 405;
        int r = idx - c * 405;
        int z = r / 81; r -= z * 81;
        int y = r / 9;  int xx = r - y * 9;
        int gz = oz + z, gy = oy + y, gx = ox + xx;
        float v = 0.f;
        if ((unsigned)gz < 32u && (unsigned)gy < 32u && (unsigned)gx < 32u)
            v = x[((c * 32 + gz) * 32 + gy) * 32 + gx];
        xt[idx] = __uint_as_float(f2tf(v));
    }
    // combine A fragments + biases
    for (int idx = tid; idx < SA2_FLOATS; idx += 256)
        ((unsigned*)sA2)[idx] = g_A2frag[idx];
    if (tid < 32) { b1s[tid] = g_bias1[tid]; b2s[tid] = g_bias2[tid]; }

    // ---- prefetch conv-A chunk 0 ----
    const unsigned* gA = g_Afrag + par * 64 * 768;   // 768 unsigned per c
    unsigned sA_base;
    {
        unsigned long long p = (unsigned long long)__cvta_generic_to_shared(sA);
        sA_base = (unsigned)p;
    }
#pragma unroll
    for (int i = 0; i < 6; i++)
        cp_async16(sA_base + (i * 256 + tid) * 16, gA + (i * 256 + tid) * 4);
    asm volatile("cp.async.commit_group;");

    // ---- per-lane B gather offsets ----
    int boff[4];
#pragma unroll
    for (int nt = 0; nt < 4; nt++) {
        int vv = 4 * w + nt;
        boff[nt] = (vv >> 3) * 81 + (vv & 7) * 9 + g;
    }
    const int toff = (t >> 1) * 9 + (t & 1);
    const unsigned* xtu = (const unsigned*)xt;

    float d[6][4][4];
#pragma unroll
    for (int i = 0; i < 6; i++)
#pragma unroll
        for (int j = 0; j < 4; j++)
#pragma unroll
            for (int r = 0; r < 4; r++) d[i][j][r] = 0.f;

    // ---- conv GEMM: K = 512 (64 c x 8 taps), 8 chunks of 8 c ----
    for (int kc = 0; kc < 8; kc++) {
        asm volatile("cp.async.wait_group 0;");
        __syncthreads();
        if (kc < 7) {
            unsigned dstS = sA_base + ((kc + 1) & 1) * 6144 * 4;
            const unsigned* src = gA + (kc + 1) * 8 * 768;
#pragma unroll
            for (int i = 0; i < 6; i++)
                cp_async16(dstS + (i * 256 + tid) * 16, src + (i * 256 + tid) * 4);
            asm volatile("cp.async.commit_group;");
        }
        const unsigned* Ab = (const unsigned*)sA + (kc & 1) * 6144;
#pragma unroll
        for (int ci = 0; ci < 8; ci++) {
            const int cbase = (kc * 8 + ci) * 405 + toff;
            unsigned b0[4], b1r[4];
#pragma unroll
            for (int nt = 0; nt < 4; nt++) {
                b0[nt] = xtu[cbase + boff[nt]];
                b1r[nt] = xtu[cbase + boff[nt] + 81];
            }
#pragma unroll
            for (int mt = 0; mt < 6; mt++) {
                unsigned a[4];
                *(uint4*)a = *(const uint4*)(Ab + ((ci * 6 + mt) * 32 + lane) * 4);
#pragma unroll
                for (int nt = 0; nt < 4; nt++)
                    mma_tf32(d[mt][nt], a, b0[nt], b1r[nt]);
            }
        }
    }

    // ---- relu + bias1, stage R[96][264] into xt region (tf32-rounded) ----
    __syncthreads();   // all B gathers from xt are done
#pragma unroll
    for (int mt = 0; mt < 6; mt++)
#pragma unroll
        for (int nt = 0; nt < 4; nt++)
#pragma unroll
            for (int r = 0; r < 4; r++) {
                int m = mt * 16 + g + 8 * (r >> 1);
                int vox = w * 32 + nt * 8 + 2 * t + (r & 1);
                float v = fmaxf(d[mt][nt][r] + b1s[m & 31], 0.f);
                ((unsigned*)xt)[m * RSTRIDE + vox] = f2tf(v);
            }
    __syncthreads();

    // ---- combine GEMM: D2[32][256] = A2[32][96] * R ----
    float e[2][4][4];
#pragma unroll
    for (int i = 0; i < 2; i++)
#pragma unroll
        for (int j = 0; j < 4; j++)
#pragma unroll
            for (int r = 0; r < 4; r++) e[i][j][r] = 0.f;

    const unsigned* Ru = (const unsigned*)xt;
#pragma unroll
    for (int k2 = 0; k2 < 12; k2++) {
        unsigned bb0[4], bb1[4];
#pragma unroll
        for (int nt = 0; nt < 4; nt++) {
            int col = w * 32 + nt * 8 + g;
            bb0[nt] = Ru[(k2 * 8 + t) * RSTRIDE + col];
            bb1[nt] = Ru[(k2 * 8 + t + 4) * RSTRIDE + col];
        }
#pragma unroll
        for (int mt = 0; mt < 2; mt++) {
            unsigned a[4];
            *(uint4*)a = *(const uint4*)((const unsigned*)sA2 +
                                         ((k2 * 2 + mt) * 32 + lane) * 4);
#pragma unroll
            for (int nt = 0; nt < 4; nt++)
                mma_tf32(e[mt][nt], a, bb0[nt], bb1[nt]);
        }
    }

    // ---- bias2 + relu + store ----
#pragma unroll
    for (int mt = 0; mt < 2; mt++)
#pragma unroll
        for (int nt = 0; nt < 4; nt++)
#pragma unroll
            for (int r = 0; r < 4; r++) {
                int o = mt * 16 + g + 8 * (r >> 1);
                int vox = w * 32 + nt * 8 + 2 * t + (r & 1);
                int vx = vox & 7, vy = (vox >> 3) & 7, vz = vox >> 6;
                int gx = 2 * (Px0 + vx) + qx;
                int gy = 2 * (Py0 + vy) + qy;
                int gz = 2 * (Pz0 + vz) + qz;
                out[o * 262144 + gz * 4096 + gy * 64 + gx] =
                    fmaxf(e[mt][nt][r] + b2s[o], 0.f);
            }
}

// ---------------- launch -----------------------------------------------------
extern "C" void kernel_launch(void* const* d_in, const int* in_sizes, int n_in,
                              void* d_out, int out_size) {
    const float* x      = (const float*)d_in[0];
    const float* w_def  = (const float*)d_in[1];
    const float* b_def  = (const float*)d_in[2];
    const float* bn1_g  = (const float*)d_in[3];
    const float* bn1_b  = (const float*)d_in[4];
    const float* bn1_m  = (const float*)d_in[5];
    const float* bn1_v  = (const float*)d_in[6];
    const float* w_comb = (const float*)d_in[7];
    const float* b_comb = (const float*)d_in[8];
    const float* bn2_g  = (const float*)d_in[9];
    const float* bn2_b  = (const float*)d_in[10];
    const float* bn2_m  = (const float*)d_in[11];
    const float* bn2_v  = (const float*)d_in[12];

    fold_params<<<1, 256>>>(b_def, bn1_g, bn1_b, bn1_m, bn1_v,
                            w_comb, b_comb, bn2_g, bn2_b, bn2_m, bn2_v);
    make_keff<<<dim3(64, 8), 192>>>(w_def, bn1_g, bn1_v);

    cudaFuncSetAttribute(conv_main, cudaFuncAttributeMaxDynamicSharedMemorySize,
                         SMEM_BYTES);
    conv_main<<<dim3(4, 4, 64), 256, SMEM_BYTES>>>(x, (float*)d_out);
}